// round 5
// baseline (speedup 1.0000x reference)
#include <cuda_runtime.h>
#include <math.h>

#define NN 50000
#define TT 1000
#define KL 5
#define KR 15
#define NC 5
#define TWOPI 6.28318530717958647692f
#define PREBLK 196
#define PRETHR 256
#define GRIDF 592
#define MAXSLAB 85

typedef unsigned long long ull;

__device__ __forceinline__ ull pk2(float lo, float hi) {
    ull r; asm("mov.b64 %0,{%1,%2};" : "=l"(r) : "f"(lo), "f"(hi)); return r;
}
__device__ __forceinline__ float2 upk2(ull v) {
    float2 f; asm("mov.b64 {%0,%1},%2;" : "=f"(f.x), "=f"(f.y) : "l"(v)); return f;
}
__device__ __forceinline__ ull ffma2(ull a, ull b, ull c) {
    ull d; asm("fma.rn.f32x2 %0,%1,%2,%3;" : "=l"(d) : "l"(a), "l"(b), "l"(c)); return d;
}

// packed per-node gather table: 16 floats (64B row): amp4, cos4, sin4, pad4
__device__ float4 g_nd[NN * 4];
// per-block partial cluster sums: [count, sumAmp*4, sumCos*4, sumSin*4] x NC
__device__ float g_partial[PREBLK * 65];
// per-node coefficients [c0, lt, a0..a3, b0..b3, 0, 0]
__device__ float g_coefs[NN * 12];

// ---------------------------------------------------------------------------
// Stage 1: per-node sincos of phases, packed node table, per-block partial
// cluster sums via 3-step warp butterfly (lanes 0..3 hold residue partials).
// No atomics, deterministic.
// ---------------------------------------------------------------------------
__global__ __launch_bounds__(PRETHR) void k_pre(const float4* __restrict__ amp,
                                                const float4* __restrict__ ph,
                                                const int* __restrict__ lab) {
    __shared__ float s_part[32 * 65];   // 8 warps x 4 residue partials
    int tid = threadIdx.x;
    int wid = tid >> 5, lane = tid & 31;
    int n = blockIdx.x * PRETHR + tid;

    float v[13];
    int c = -1;
    if (n < NN) {
        float4 p = ph[n];
        float4 cs, sn;
        __sincosf(p.x, &sn.x, &cs.x);
        __sincosf(p.y, &sn.y, &cs.y);
        __sincosf(p.z, &sn.z, &cs.z);
        __sincosf(p.w, &sn.w, &cs.w);
        float4 a = amp[n];
        g_nd[n * 4 + 0] = a;
        g_nd[n * 4 + 1] = cs;
        g_nd[n * 4 + 2] = sn;
        c = lab[n];
        v[0] = 1.f;
        v[1] = a.x;  v[2] = a.y;  v[3] = a.z;  v[4] = a.w;
        v[5] = cs.x; v[6] = cs.y; v[7] = cs.z; v[8] = cs.w;
        v[9] = sn.x; v[10] = sn.y; v[11] = sn.z; v[12] = sn.w;
    } else {
        #pragma unroll
        for (int i = 0; i < 13; i++) v[i] = 0.f;
    }

    #pragma unroll
    for (int cc = 0; cc < NC; cc++) {
        #pragma unroll
        for (int i = 0; i < 13; i++) {
            float x = (c == cc) ? v[i] : 0.f;
            x += __shfl_xor_sync(0xffffffffu, x, 16);
            x += __shfl_xor_sync(0xffffffffu, x, 8);
            x += __shfl_xor_sync(0xffffffffu, x, 4);
            // lane l now holds sum over lanes == l (mod 4); lanes 0..3 cover all
            if (lane < 4) s_part[(wid * 4 + lane) * 65 + cc * 13 + i] = x;
        }
    }
    __syncthreads();
    if (tid < 65) {
        float s = 0.f;
        #pragma unroll
        for (int w = 0; w < 32; w++) s += s_part[w * 65 + tid];
        g_partial[blockIdx.x * 65 + tid] = s;
    }
}

// ---------------------------------------------------------------------------
// Stage 2: reduce cluster partials, precompute cluster circular means once per
// block, then per-node message passing -> harmonic coefficients. Gathers hit
// the packed 64B node rows (2 L2 sectors/neighbor instead of 3).
// ---------------------------------------------------------------------------
__global__ __launch_bounds__(256) void k_coef(const float* __restrict__ amp,
                                              const float* __restrict__ ph,
                                              const float* __restrict__ lw,
                                              const float* __restrict__ rw,
                                              const int* __restrict__ li,
                                              const int* __restrict__ ri,
                                              const int* __restrict__ lab,
                                              const float* __restrict__ co,
                                              const float* __restrict__ lt) {
    __shared__ float s_cl[65];
    __shared__ float s_mA[NC * 4];
    __shared__ float s_cPh[NC * 4];
    __shared__ int   s_big[NC];
    int tid = threadIdx.x;

    if (tid < 65) {
        float s = 0.f;
        for (int r = 0; r < PREBLK; r++) s += g_partial[r * 65 + tid];
        s_cl[tid] = s;
    }
    __syncthreads();
    if (tid < NC * 4) {
        int c = tid >> 2, i = tid & 3;
        float cnt = s_cl[c * 13];
        if (i == 0) s_big[c] = (cnt > 1.0f);
        s_mA[tid]  = s_cl[c * 13 + 1 + i] / fmaxf(cnt, 1.f);
        s_cPh[tid] = atan2f(s_cl[c * 13 + 9 + i], s_cl[c * 13 + 5 + i]);
    }
    __syncthreads();

    int n = blockIdx.x * 256 + tid;
    if (n >= NN) return;

    const ulonglong2* ndP = (const ulonglong2*)g_nd;  // row j = ndP[j*4 + 0..2]

    float4 a4 = ((const float4*)amp)[n];
    float4 p4 = ((const float4*)ph)[n];

    ull la01 = 0, la23 = 0, lc01 = 0, lc23 = 0, ls01 = 0, ls23 = 0;
    ull ra01 = 0, ra23 = 0, rc01 = 0, rc23 = 0, rs01 = 0, rs23 = 0;

    #pragma unroll
    for (int k = 0; k < KL; k++) {
        int j = li[n * KL + k];
        float w = lw[n * KL + k];
        ull wP = pk2(w, w);
        ulonglong2 aj = ndP[j * 4 + 0];
        ulonglong2 cj = ndP[j * 4 + 1];
        ulonglong2 sj = ndP[j * 4 + 2];
        la01 = ffma2(aj.x, wP, la01); la23 = ffma2(aj.y, wP, la23);
        lc01 = ffma2(cj.x, wP, lc01); lc23 = ffma2(cj.y, wP, lc23);
        ls01 = ffma2(sj.x, wP, ls01); ls23 = ffma2(sj.y, wP, ls23);
    }
    #pragma unroll
    for (int k = 0; k < KR; k++) {
        int j = ri[n * KR + k];
        float w = rw[n * KR + k];
        ull wP = pk2(w, w);
        ulonglong2 aj = ndP[j * 4 + 0];
        ulonglong2 cj = ndP[j * 4 + 1];
        ulonglong2 sj = ndP[j * 4 + 2];
        ra01 = ffma2(aj.x, wP, ra01); ra23 = ffma2(aj.y, wP, ra23);
        rc01 = ffma2(cj.x, wP, rc01); rc23 = ffma2(cj.y, wP, rc23);
        rs01 = ffma2(sj.x, wP, rs01); rs23 = ffma2(sj.y, wP, rs23);
    }

    float2 t;
    float la[4], lc[4], ls[4], ra[4], rc[4], rs[4];
    t = upk2(la01); la[0] = t.x; la[1] = t.y;  t = upk2(la23); la[2] = t.x; la[3] = t.y;
    t = upk2(lc01); lc[0] = t.x; lc[1] = t.y;  t = upk2(lc23); lc[2] = t.x; lc[3] = t.y;
    t = upk2(ls01); ls[0] = t.x; ls[1] = t.y;  t = upk2(ls23); ls[2] = t.x; ls[3] = t.y;
    t = upk2(ra01); ra[0] = t.x; ra[1] = t.y;  t = upk2(ra23); ra[2] = t.x; ra[3] = t.y;
    t = upk2(rc01); rc[0] = t.x; rc[1] = t.y;  t = upk2(rc23); rc[2] = t.x; rc[3] = t.y;
    t = upk2(rs01); rs[0] = t.x; rs[1] = t.y;  t = upk2(rs23); rs[2] = t.x; rs[3] = t.y;

    int c = lab[n];
    bool big = s_big[c];
    float aP[4] = {a4.x, a4.y, a4.z, a4.w};
    float pP[4] = {p4.x, p4.y, p4.z, p4.w};
    float outv[12];
    outv[0] = co[n];
    outv[1] = lt[n];
    #pragma unroll
    for (int i = 0; i < 4; i++) {
        float campU = big ? s_mA[c * 4 + i] : aP[i];
        // combined = 0.5*local + 0.3*(0.7*regional_sum) + 0.2*cluster
        float ampO = 0.7f * aP[i] + 0.3f * (0.5f * la[i] + 0.21f * ra[i] + 0.2f * campU);
        float cphU = big ? s_cPh[c * 4 + i] : pP[i];
        float phL = atan2f(ls[i], lc[i]);
        float phR = atan2f(rs[i], rc[i]);
        float phO = 0.7f * pP[i] + 0.3f * (0.5f * phL + 0.3f * phR + 0.2f * cphU);
        float s, cc;
        __sincosf(phO, &s, &cc);
        outv[2 + i] = ampO * cc;  // coeff of sin(w t)
        outv[6 + i] = ampO * s;   // coeff of cos(w t)
    }
    outv[10] = 0.f; outv[11] = 0.f;
    float4* dst = (float4*)(g_coefs + n * 12);
    dst[0] = make_float4(outv[0], outv[1], outv[2], outv[3]);
    dst[1] = make_float4(outv[4], outv[5], outv[6], outv[7]);
    dst[2] = make_float4(outv[8], outv[9], outv[10], outv[11]);
}

// ---------------------------------------------------------------------------
// Stage 3: 200MB fill, balanced slabs (592 blocks = 148 SMs x 4, one wave).
// out[n,t] = c0 + lt*t + sum_i a_i*sin(w_i t) + b_i*cos(w_i t), f32x2 packed.
// ---------------------------------------------------------------------------
__global__ __launch_bounds__(256, 4) void k_fill(const float* __restrict__ tv,
                                                 float* __restrict__ out) {
    __shared__ ulonglong2 s_cp[MAXSLAB * 5];
    int start = (int)(((long long)blockIdx.x * NN) / GRIDF);
    int end   = (int)(((long long)(blockIdx.x + 1) * NN) / GRIDF);
    int nn = end - start;
    {
        ull* s_raw = (ull*)s_cp;
        for (int i = threadIdx.x; i < nn * 10; i += 256) {
            int node = i / 10, s = i - node * 10;
            float v = g_coefs[(start + node) * 12 + s];
            s_raw[node * 10 + s] = pk2(v, v);
        }
    }
    __syncthreads();

    int t0 = threadIdx.x * 4;
    if (t0 >= TT) return;  // threads 250..255 only helped staging

    float4 tvv = ((const float4*)tv)[threadIdx.x];
    ull T01 = pk2(tvv.x, tvv.y);
    ull T23 = pk2(tvv.z, tvv.w);

    const float w[4] = {TWOPI * 4.f, TWOPI * 2.f, TWOPI, TWOPI * 0.5f};
    ull S01[4], C01[4], S23[4], C23[4];
    #pragma unroll
    for (int i = 0; i < 4; i++) {
        float s0, c0, s1, c1, s2, c2, s3, c3;
        sincosf(w[i] * tvv.x, &s0, &c0);
        sincosf(w[i] * tvv.y, &s1, &c1);
        sincosf(w[i] * tvv.z, &s2, &c2);
        sincosf(w[i] * tvv.w, &s3, &c3);
        S01[i] = pk2(s0, s1); C01[i] = pk2(c0, c1);
        S23[i] = pk2(s2, s3); C23[i] = pk2(c2, c3);
    }

    #pragma unroll 2
    for (int j = 0; j < nn; j++) {
        ulonglong2 e0 = s_cp[j * 5 + 0];
        ulonglong2 e1 = s_cp[j * 5 + 1];
        ulonglong2 e2 = s_cp[j * 5 + 2];
        ulonglong2 e3 = s_cp[j * 5 + 3];
        ulonglong2 e4 = s_cp[j * 5 + 4];
        ull r0 = ffma2(e0.y, T01, e0.x);
        r0 = ffma2(e1.x, S01[0], r0); r0 = ffma2(e1.y, S01[1], r0);
        r0 = ffma2(e2.x, S01[2], r0); r0 = ffma2(e2.y, S01[3], r0);
        r0 = ffma2(e3.x, C01[0], r0); r0 = ffma2(e3.y, C01[1], r0);
        r0 = ffma2(e4.x, C01[2], r0); r0 = ffma2(e4.y, C01[3], r0);
        ull r1 = ffma2(e0.y, T23, e0.x);
        r1 = ffma2(e1.x, S23[0], r1); r1 = ffma2(e1.y, S23[1], r1);
        r1 = ffma2(e2.x, S23[2], r1); r1 = ffma2(e2.y, S23[3], r1);
        r1 = ffma2(e3.x, C23[0], r1); r1 = ffma2(e3.y, C23[1], r1);
        r1 = ffma2(e4.x, C23[2], r1); r1 = ffma2(e4.y, C23[3], r1);
        ulonglong2 o; o.x = r0; o.y = r1;
        *reinterpret_cast<ulonglong2*>(out + (size_t)(start + j) * TT + t0) = o;
    }
}

extern "C" void kernel_launch(void* const* d_in, const int* in_sizes, int n_in,
                              void* d_out, int out_size) {
    const float* tv  = (const float*)d_in[0];  // time_vector        [1000]
    const float* co  = (const float*)d_in[1];  // constant_offset    [50000]
    const float* lt  = (const float*)d_in[2];  // linear_trend       [50000]
    const float* amp = (const float*)d_in[3];  // seasonal_amplitudes[50000,4]
    const float* ph  = (const float*)d_in[4];  // seasonal_phases    [50000,4]
    const float* lw  = (const float*)d_in[5];  // local_w            [50000,5]
    const float* rw  = (const float*)d_in[6];  // regional_w         [50000,15]
    const int*   li  = (const int*)d_in[7];    // local_idx          [50000,5]
    const int*   ri  = (const int*)d_in[8];    // regional_idx       [50000,15]
    const int*   lab = (const int*)d_in[9];    // cluster_labels     [50000]
    float* out = (float*)d_out;

    k_pre<<<PREBLK, PRETHR>>>((const float4*)amp, (const float4*)ph, lab);
    k_coef<<<(NN + 255) / 256, 256>>>(amp, ph, lw, rw, li, ri, lab, co, lt);
    k_fill<<<GRIDF, 256>>>(tv, out);
}

// round 7
// speedup vs baseline: 1.1219x; 1.1219x over previous
#include <cuda_runtime.h>
#include <math.h>

#define NN 50000
#define TT 1000
#define KL 5
#define KR 15
#define NC 5
#define TWOPI 6.28318530717958647692f
#define PREG 148
#define PRETHR 512
#define GRIDF 592
#define MAXSLAB 85

typedef unsigned long long ull;

__device__ __forceinline__ ull pk2(float lo, float hi) {
    ull r; asm("mov.b64 %0,{%1,%2};" : "=l"(r) : "f"(lo), "f"(hi)); return r;
}
__device__ __forceinline__ float2 upk2(ull v) {
    float2 f; asm("mov.b64 {%0,%1},%2;" : "=f"(f.x), "=f"(f.y) : "l"(v)); return f;
}
__device__ __forceinline__ ull ffma2(ull a, ull b, ull c) {
    ull d; asm("fma.rn.f32x2 %0,%1,%2,%3;" : "=l"(d) : "l"(a), "l"(b), "l"(c)); return d;
}

// packed 64B node rows: [float4 amp][float4 cos][float4 sin][pad]
__device__ float4 g_nd[NN * 4];
// per-block partial cluster sums: [count, sumAmp*4, sumCos*4, sumSin*4] x NC
__device__ float g_partial[PREG * 65];
// finalized cluster stats: [0..19] meanAmp, [20..39] circPhase, [40..44] big flag
__device__ float g_cmeans[48];
__device__ unsigned g_arr;  // arrival counter; reset by last block each launch

// ---------------------------------------------------------------------------
// Stage 1: per-node sincos -> packed fp32 node table; per-block cluster
// partials via 3-step warp butterfly; LAST block reduces to g_cmeans.
// Deterministic (fixed-order reductions), replay-safe (counter reset).
// ---------------------------------------------------------------------------
__global__ __launch_bounds__(PRETHR) void k_pre(const float4* __restrict__ amp,
                                                const float4* __restrict__ ph,
                                                const int* __restrict__ lab) {
    __shared__ float s_part[64 * 65];   // 16 warps x 4 residue rows
    __shared__ float s_cl[65];
    __shared__ unsigned s_last;
    int tid = threadIdx.x;
    int wid = tid >> 5, lane = tid & 31;
    int n = blockIdx.x * PRETHR + tid;

    float v[13];
    int c = -1;
    if (n < NN) {
        float4 p = ph[n];
        float4 cs, sn;
        __sincosf(p.x, &sn.x, &cs.x);
        __sincosf(p.y, &sn.y, &cs.y);
        __sincosf(p.z, &sn.z, &cs.z);
        __sincosf(p.w, &sn.w, &cs.w);
        float4 a = amp[n];
        g_nd[n * 4 + 0] = a;
        g_nd[n * 4 + 1] = cs;
        g_nd[n * 4 + 2] = sn;
        c = lab[n];
        v[0] = 1.f;
        v[1] = a.x;  v[2] = a.y;  v[3] = a.z;  v[4] = a.w;
        v[5] = cs.x; v[6] = cs.y; v[7] = cs.z; v[8] = cs.w;
        v[9] = sn.x; v[10] = sn.y; v[11] = sn.z; v[12] = sn.w;
    } else {
        #pragma unroll
        for (int i = 0; i < 13; i++) v[i] = 0.f;
    }

    #pragma unroll
    for (int cc = 0; cc < NC; cc++) {
        #pragma unroll
        for (int i = 0; i < 13; i++) {
            float x = (c == cc) ? v[i] : 0.f;
            x += __shfl_xor_sync(0xffffffffu, x, 16);
            x += __shfl_xor_sync(0xffffffffu, x, 8);
            x += __shfl_xor_sync(0xffffffffu, x, 4);
            if (lane < 4) s_part[(wid * 4 + lane) * 65 + cc * 13 + i] = x;
        }
    }
    __syncthreads();
    if (tid < 65) {
        float s = 0.f;
        #pragma unroll
        for (int w = 0; w < 64; w++) s += s_part[w * 65 + tid];
        g_partial[blockIdx.x * 65 + tid] = s;
    }
    __threadfence();
    __syncthreads();
    if (tid == 0) {
        unsigned o = atomicAdd(&g_arr, 1u);
        s_last = (o == PREG - 1) ? 1u : 0u;
    }
    __syncthreads();
    if (s_last) {
        __threadfence();
        if (tid < 65) {
            float s = 0.f;
            for (int r = 0; r < PREG; r++) s += g_partial[r * 65 + tid];
            s_cl[tid] = s;
        }
        __syncthreads();
        if (tid < 20) {
            int cc = tid >> 2, i = tid & 3;
            float cnt = s_cl[cc * 13];
            g_cmeans[tid]      = s_cl[cc * 13 + 1 + i] / fmaxf(cnt, 1.f);
            g_cmeans[20 + tid] = atan2f(s_cl[cc * 13 + 9 + i], s_cl[cc * 13 + 5 + i]);
            if (i == 0) g_cmeans[40 + cc] = (cnt > 1.f) ? 1.f : 0.f;
        }
        if (tid == 0) g_arr = 0u;   // reset for next graph replay
    }
}

// ---------------------------------------------------------------------------
// Stage 2 (fused coef + fill). Block b owns slab of <=85 nodes.
//   phase A: 3 threads per node gather (local | regional 0-7 | regional 8-14)
//            from 64B packed fp32 rows (3 LDG.128).
//   phase B: owner thread merges partials, atan2/sincos -> packed coeffs in
//            shared (pre-duplicated f32x2).
//   phase C: 250 threads x 4 t-values fill <=85 x 1000 outputs, f32x2 chain.
// ---------------------------------------------------------------------------
__global__ __launch_bounds__(256, 4) void k_fused(const float* __restrict__ tv,
                                                  const float* __restrict__ co,
                                                  const float* __restrict__ lt,
                                                  const float* __restrict__ amp,
                                                  const float* __restrict__ ph,
                                                  const float* __restrict__ lw,
                                                  const float* __restrict__ rw,
                                                  const int* __restrict__ li,
                                                  const int* __restrict__ ri,
                                                  const int* __restrict__ lab,
                                                  float* __restrict__ out) {
    __shared__ float s_cm[48];
    __shared__ ull s_pp[MAXSLAB * 12];       // chunk1/2 regional partials
    __shared__ ulonglong2 s_cp[MAXSLAB * 5]; // dup-packed coefficients
    int tid = threadIdx.x;
    int start = (int)(((long long)blockIdx.x * NN) / GRIDF);
    int end   = (int)(((long long)(blockIdx.x + 1) * NN) / GRIDF);
    int nn = end - start;

    if (tid < 48) s_cm[tid] = g_cmeans[tid];

    int node = -1, chunk = 0;
    if (tid < nn)          { node = tid;          chunk = 0; }
    else if (tid < 2 * nn) { node = tid - nn;     chunk = 1; }
    else if (tid < 3 * nn) { node = tid - 2 * nn; chunk = 2; }

    const ulonglong2* ndA = (const ulonglong2*)g_nd;  // row j = ndA[j*4 + 0..2]

    // owner-persistent state
    ull la01 = 0, la23 = 0, lc01 = 0, lc23 = 0, ls01 = 0, ls23 = 0;
    float4 a4, p4;
    float cov = 0.f, ltv = 0.f;
    int c = 0;

    if (node >= 0) {
        int gn = start + node;
        if (chunk == 0) {
            a4 = ((const float4*)amp)[gn];
            p4 = ((const float4*)ph)[gn];
            cov = co[gn]; ltv = lt[gn]; c = lab[gn];
            #pragma unroll
            for (int k = 0; k < KL; k++) {
                int j = li[gn * KL + k];
                float w = lw[gn * KL + k];
                ull wP = pk2(w, w);
                ulonglong2 aj = ndA[j * 4 + 0];
                ulonglong2 cj = ndA[j * 4 + 1];
                ulonglong2 sj = ndA[j * 4 + 2];
                la01 = ffma2(aj.x, wP, la01); la23 = ffma2(aj.y, wP, la23);
                lc01 = ffma2(cj.x, wP, lc01); lc23 = ffma2(cj.y, wP, lc23);
                ls01 = ffma2(sj.x, wP, ls01); ls23 = ffma2(sj.y, wP, ls23);
            }
        } else {
            int kb = (chunk == 1) ? 0 : 8;
            int ke = (chunk == 1) ? 8 : KR;
            ull r0 = 0, r1 = 0, r2 = 0, r3 = 0, r4 = 0, r5 = 0;
            for (int k = kb; k < ke; k++) {
                int j = ri[gn * KR + k];
                float w = rw[gn * KR + k];
                ull wP = pk2(w, w);
                ulonglong2 aj = ndA[j * 4 + 0];
                ulonglong2 cj = ndA[j * 4 + 1];
                ulonglong2 sj = ndA[j * 4 + 2];
                r0 = ffma2(aj.x, wP, r0); r1 = ffma2(aj.y, wP, r1);
                r2 = ffma2(cj.x, wP, r2); r3 = ffma2(cj.y, wP, r3);
                r4 = ffma2(sj.x, wP, r4); r5 = ffma2(sj.y, wP, r5);
            }
            ull* dst = &s_pp[node * 12 + (chunk - 1) * 6];
            dst[0] = r0; dst[1] = r1; dst[2] = r2;
            dst[3] = r3; dst[4] = r4; dst[5] = r5;
        }
    }
    __syncthreads();

    if (node >= 0 && chunk == 0) {
        // merge regional partials
        float ra[4], rc[4], rs[4];
        {
            const ull* p1 = &s_pp[node * 12];
            const ull* p2 = p1 + 6;
            float2 x, y;
            x = upk2(p1[0]); y = upk2(p2[0]); ra[0] = x.x + y.x; ra[1] = x.y + y.y;
            x = upk2(p1[1]); y = upk2(p2[1]); ra[2] = x.x + y.x; ra[3] = x.y + y.y;
            x = upk2(p1[2]); y = upk2(p2[2]); rc[0] = x.x + y.x; rc[1] = x.y + y.y;
            x = upk2(p1[3]); y = upk2(p2[3]); rc[2] = x.x + y.x; rc[3] = x.y + y.y;
            x = upk2(p1[4]); y = upk2(p2[4]); rs[0] = x.x + y.x; rs[1] = x.y + y.y;
            x = upk2(p1[5]); y = upk2(p2[5]); rs[2] = x.x + y.x; rs[3] = x.y + y.y;
        }
        float la[4], lc[4], ls[4];
        float2 t;
        t = upk2(la01); la[0] = t.x; la[1] = t.y;  t = upk2(la23); la[2] = t.x; la[3] = t.y;
        t = upk2(lc01); lc[0] = t.x; lc[1] = t.y;  t = upk2(lc23); lc[2] = t.x; lc[3] = t.y;
        t = upk2(ls01); ls[0] = t.x; ls[1] = t.y;  t = upk2(ls23); ls[2] = t.x; ls[3] = t.y;

        bool big = s_cm[40 + c] > 0.5f;
        float aP[4] = {a4.x, a4.y, a4.z, a4.w};
        float pP[4] = {p4.x, p4.y, p4.z, p4.w};
        float av[4], bv[4];
        #pragma unroll
        for (int i = 0; i < 4; i++) {
            float campU = big ? s_cm[c * 4 + i] : aP[i];
            // combined = 0.5*local + 0.3*(0.7*regional_sum) + 0.2*cluster
            float ampO = 0.7f * aP[i] + 0.3f * (0.5f * la[i] + 0.21f * ra[i] + 0.2f * campU);
            float cphU = big ? s_cm[20 + c * 4 + i] : pP[i];
            float phL = atan2f(ls[i], lc[i]);
            float phR = atan2f(rs[i], rc[i]);
            float phO = 0.7f * pP[i] + 0.3f * (0.5f * phL + 0.3f * phR + 0.2f * cphU);
            float s, cc2;
            __sincosf(phO, &s, &cc2);
            av[i] = ampO * cc2;
            bv[i] = ampO * s;
        }
        ull* q = (ull*)&s_cp[node * 5];
        q[0] = pk2(cov, cov);     q[1] = pk2(ltv, ltv);
        q[2] = pk2(av[0], av[0]); q[3] = pk2(av[1], av[1]);
        q[4] = pk2(av[2], av[2]); q[5] = pk2(av[3], av[3]);
        q[6] = pk2(bv[0], bv[0]); q[7] = pk2(bv[1], bv[1]);
        q[8] = pk2(bv[2], bv[2]); q[9] = pk2(bv[3], bv[3]);
    }
    __syncthreads();

    int t0 = tid * 4;
    if (t0 >= TT) return;  // threads 250..255 already did their shared-memory duty

    float4 tvv = ((const float4*)tv)[tid];
    ull T01 = pk2(tvv.x, tvv.y);
    ull T23 = pk2(tvv.z, tvv.w);

    const float w[4] = {TWOPI * 4.f, TWOPI * 2.f, TWOPI, TWOPI * 0.5f};
    ull S01[4], C01[4], S23[4], C23[4];
    #pragma unroll
    for (int i = 0; i < 4; i++) {
        float s0, c0, s1, c1, s2, c2, s3, c3;
        sincosf(w[i] * tvv.x, &s0, &c0);
        sincosf(w[i] * tvv.y, &s1, &c1);
        sincosf(w[i] * tvv.z, &s2, &c2);
        sincosf(w[i] * tvv.w, &s3, &c3);
        S01[i] = pk2(s0, s1); C01[i] = pk2(c0, c1);
        S23[i] = pk2(s2, s3); C23[i] = pk2(c2, c3);
    }

    #pragma unroll 2
    for (int j = 0; j < nn; j++) {
        ulonglong2 e0 = s_cp[j * 5 + 0];
        ulonglong2 e1 = s_cp[j * 5 + 1];
        ulonglong2 e2 = s_cp[j * 5 + 2];
        ulonglong2 e3 = s_cp[j * 5 + 3];
        ulonglong2 e4 = s_cp[j * 5 + 4];
        ull r0 = ffma2(e0.y, T01, e0.x);
        r0 = ffma2(e1.x, S01[0], r0); r0 = ffma2(e1.y, S01[1], r0);
        r0 = ffma2(e2.x, S01[2], r0); r0 = ffma2(e2.y, S01[3], r0);
        r0 = ffma2(e3.x, C01[0], r0); r0 = ffma2(e3.y, C01[1], r0);
        r0 = ffma2(e4.x, C01[2], r0); r0 = ffma2(e4.y, C01[3], r0);
        ull r1 = ffma2(e0.y, T23, e0.x);
        r1 = ffma2(e1.x, S23[0], r1); r1 = ffma2(e1.y, S23[1], r1);
        r1 = ffma2(e2.x, S23[2], r1); r1 = ffma2(e2.y, S23[3], r1);
        r1 = ffma2(e3.x, C23[0], r1); r1 = ffma2(e3.y, C23[1], r1);
        r1 = ffma2(e4.x, C23[2], r1); r1 = ffma2(e4.y, C23[3], r1);
        ulonglong2 o; o.x = r0; o.y = r1;
        *reinterpret_cast<ulonglong2*>(out + (size_t)(start + j) * TT + t0) = o;
    }
}

extern "C" void kernel_launch(void* const* d_in, const int* in_sizes, int n_in,
                              void* d_out, int out_size) {
    const float* tv  = (const float*)d_in[0];  // time_vector        [1000]
    const float* co  = (const float*)d_in[1];  // constant_offset    [50000]
    const float* lt  = (const float*)d_in[2];  // linear_trend       [50000]
    const float* amp = (const float*)d_in[3];  // seasonal_amplitudes[50000,4]
    const float* ph  = (const float*)d_in[4];  // seasonal_phases    [50000,4]
    const float* lw  = (const float*)d_in[5];  // local_w            [50000,5]
    const float* rw  = (const float*)d_in[6];  // regional_w         [50000,15]
    const int*   li  = (const int*)d_in[7];    // local_idx          [50000,5]
    const int*   ri  = (const int*)d_in[8];    // regional_idx       [50000,15]
    const int*   lab = (const int*)d_in[9];    // cluster_labels     [50000]
    float* out = (float*)d_out;

    k_pre<<<PREG, PRETHR>>>((const float4*)amp, (const float4*)ph, lab);
    k_fused<<<GRIDF, 256>>>(tv, co, lt, amp, ph, lw, rw, li, ri, lab, out);
}